// round 9
// baseline (speedup 1.0000x reference)
#include <cuda_runtime.h>
#include <cuda_bf16.h>
#include <math.h>

#define N_NODES 50000
#define DIM     64
#define NHEAD   8
#define NEDGE   800000
#define NEG_SLOPE 0.2f

#define SCAN_BLK  1024
#define SCAN_NBLK ((N_NODES + SCAN_BLK - 1) / SCAN_BLK)   // 49

// Scratch (device globals). INVARIANT: g_deg zero at module load and re-zeroed
// by fill_kernel each call.
__device__ float g_sdst[N_NODES * NHEAD];
__device__ float g_ssrc[N_NODES * NHEAD];
__device__ int   g_deg[N_NODES];
__device__ int   g_row[N_NODES + 1];
__device__ int   g_cursor[N_NODES];
__device__ int   g_csr_src[NEDGE];
__device__ float g_csr_ex[(size_t)NEDGE * NHEAD];

__device__ __forceinline__ float lrelu(float v) {
    return v >= 0.0f ? v : NEG_SLOPE * v;
}

// packed fp32x2 FMA: acc = x * ee + acc  (elementwise on 2 packed floats)
__device__ __forceinline__ void fma2(unsigned long long& acc,
                                     unsigned long long x,
                                     unsigned long long ee) {
    asm("fma.rn.f32x2 %0, %1, %2, %0;" : "+l"(acc) : "l"(x), "l"(ee));
}
__device__ __forceinline__ unsigned long long bcast2(float e) {
    unsigned long long r;
    asm("mov.b64 %0, {%1, %1};" : "=l"(r) : "f"(e));
    return r;
}

// ---------------------------------------------------------------------------
// Kernel 1: per-node scores (warp computes 2 nodes) + fused degree histogram.
__global__ void scores_hist_kernel(const float* __restrict__ h_t,
                                   const float* __restrict__ att,
                                   const int* __restrict__ ei) {
    __shared__ float s_att[NHEAD * 2 * DIM];
    for (int i = threadIdx.x; i < NHEAD * 2 * DIM; i += blockDim.x)
        s_att[i] = att[i];
    __syncthreads();

    int idx = blockIdx.x * blockDim.x + threadIdx.x;
    if (idx >= NEDGE) return;

    atomicAdd(&g_deg[ei[NEDGE + idx]], 1);

    int lane = threadIdx.x & 31;
    int half = lane >> 4;
    int sub  = lane & 15;
    int n = (idx >> 5) * 2 + half;

    const float4 x = ((const float4*)(h_t + (size_t)n * DIM))[sub];

    float acc[16];
#pragma unroll
    for (int c = 0; c < 16; c++) {
        const float4 a = *(const float4*)(s_att + (c & 7) * 128 + (c >> 3) * 64 + sub * 4);
        acc[c] = x.x * a.x + x.y * a.y + x.z * a.z + x.w * a.w;
    }
#pragma unroll
    for (int o = 8; o > 0; o >>= 1) {
#pragma unroll
        for (int c = 0; c < 16; c++)
            acc[c] += __shfl_xor_sync(0xffffffffu, acc[c], o);
    }
    if (sub == 0) {
        float4* pd = (float4*)(g_sdst + n * NHEAD);
        float4* ps = (float4*)(g_ssrc + n * NHEAD);
        pd[0] = make_float4(acc[0], acc[1], acc[2], acc[3]);
        pd[1] = make_float4(acc[4], acc[5], acc[6], acc[7]);
        ps[0] = make_float4(acc[8], acc[9], acc[10], acc[11]);
        ps[1] = make_float4(acc[12], acc[13], acc[14], acc[15]);
    }
}

// ---------------------------------------------------------------------------
// Kernel 2: single-kernel scan; each block self-computes its prefix.
__global__ void scan_kernel() {
    __shared__ int sh[SCAN_BLK];
    __shared__ int red[32];
    __shared__ int s_boff;
    int t = threadIdx.x;
    int bid = blockIdx.x;

    int limit = bid * SCAN_BLK;
    int acc = 0;
    for (int i = t; i < limit; i += SCAN_BLK) acc += g_deg[i];
#pragma unroll
    for (int o = 16; o > 0; o >>= 1)
        acc += __shfl_down_sync(0xffffffffu, acc, o);
    if ((t & 31) == 0) red[t >> 5] = acc;
    __syncthreads();
    if (t < 32) {
        int w = red[t];
#pragma unroll
        for (int o = 16; o > 0; o >>= 1)
            w += __shfl_down_sync(0xffffffffu, w, o);
        if (t == 0) s_boff = w;
    }

    int i = bid * SCAN_BLK + t;
    int d = (i < N_NODES) ? g_deg[i] : 0;
    sh[t] = d;
    __syncthreads();
    for (int o = 1; o < SCAN_BLK; o <<= 1) {
        int u = (t >= o) ? sh[t - o] : 0;
        __syncthreads();
        sh[t] += u;
        __syncthreads();
    }
    if (i < N_NODES) {
        int excl = s_boff + sh[t] - d;
        g_row[i] = excl;
        g_cursor[i] = excl;
    }
    if (i == N_NODES - 1) g_row[N_NODES] = NEDGE;
}

// ---------------------------------------------------------------------------
// Kernel 3: fill CSR + per-edge exp for 8 heads; re-zero g_deg.
__global__ void fill_kernel(const int* __restrict__ ei) {
    int e = blockIdx.x * blockDim.x + threadIdx.x;
    if (e < N_NODES) g_deg[e] = 0;
    if (e >= NEDGE) return;
    int src = ei[e];
    int dst = ei[NEDGE + e];
    int p = atomicAdd(&g_cursor[dst], 1);
    g_csr_src[p] = src;

    const float4* pd = (const float4*)(g_sdst + dst * NHEAD);
    const float4* ps = (const float4*)(g_ssrc + src * NHEAD);
    float4 d0 = pd[0], d1 = pd[1];
    float4 s0 = ps[0], s1 = ps[1];
    float4 e0, e1;
    e0.x = __expf(lrelu(d0.x + s0.x));
    e0.y = __expf(lrelu(d0.y + s0.y));
    e0.z = __expf(lrelu(d0.z + s0.z));
    e0.w = __expf(lrelu(d0.w + s0.w));
    e1.x = __expf(lrelu(d1.x + s1.x));
    e1.y = __expf(lrelu(d1.y + s1.y));
    e1.z = __expf(lrelu(d1.z + s1.z));
    e1.w = __expf(lrelu(d1.w + s1.w));
    float4* pe = (float4*)(g_csr_ex + (size_t)p * NHEAD);
    pe[0] = e0;
    pe[1] = e1;
}

// ---------------------------------------------------------------------------
// Kernel 4: aggregation + normalize + ELU. One warp per node.
// lane (h=lane>>2, q=lane&3) owns bytes {0,16,128,144} at row base + q*32
// (single 128B line per LDG.128, immediate offsets). Accumulation in packed
// fp32x2 via fma.rn.f32x2 (8 FFMA2/edge/lane instead of 16 FFMA).
__global__ void __launch_bounds__(128, 8)
node_agg_kernel(const float* __restrict__ h_t, float* __restrict__ out) {
    int warp = (blockIdx.x * blockDim.x + threadIdx.x) >> 5;
    if (warp >= N_NODES) return;
    int lane = threadIdx.x & 31;
    int n = warp;
    int rs = g_row[n];
    int re = g_row[n + 1];

    int h = lane >> 2;
    int q = lane & 3;
    const char* hbase = (const char*)h_t + q * 32;   // + s*256 per edge

    unsigned long long A[8] = {0, 0, 0, 0, 0, 0, 0, 0};
    float denom = 0.0f;

    for (int base = rs; base < re; base += 32) {
        int cnt = re - base; if (cnt > 32) cnt = 32;
        int s = (lane < cnt) ? g_csr_src[base + lane] : 0;
        // ex pointer for this chunk: advance by 32B per edge (immediate-friendly)
        const char* exp0 = (const char*)(g_csr_ex + (size_t)base * NHEAD + h);

        int j = 0;
        for (; j + 2 <= cnt; j += 2) {
            int s0 = __shfl_sync(0xffffffffu, s, j);
            int s1 = __shfl_sync(0xffffffffu, s, j + 1);
            float e0 = *(const float*)(exp0 + (size_t)j * 32);
            float e1 = *(const float*)(exp0 + (size_t)j * 32 + 32);

            const char* r0 = hbase + ((size_t)s0 << 8);
            const char* r1 = hbase + ((size_t)s1 << 8);
            longlong2 u00 = *(const longlong2*)(r0);
            longlong2 u01 = *(const longlong2*)(r0 + 16);
            longlong2 u02 = *(const longlong2*)(r0 + 128);
            longlong2 u03 = *(const longlong2*)(r0 + 144);
            longlong2 u10 = *(const longlong2*)(r1);
            longlong2 u11 = *(const longlong2*)(r1 + 16);
            longlong2 u12 = *(const longlong2*)(r1 + 128);
            longlong2 u13 = *(const longlong2*)(r1 + 144);

            unsigned long long ee0 = bcast2(e0);
            unsigned long long ee1 = bcast2(e1);
            denom += e0 + e1;

            fma2(A[0], (unsigned long long)u00.x, ee0);
            fma2(A[1], (unsigned long long)u00.y, ee0);
            fma2(A[2], (unsigned long long)u01.x, ee0);
            fma2(A[3], (unsigned long long)u01.y, ee0);
            fma2(A[4], (unsigned long long)u02.x, ee0);
            fma2(A[5], (unsigned long long)u02.y, ee0);
            fma2(A[6], (unsigned long long)u03.x, ee0);
            fma2(A[7], (unsigned long long)u03.y, ee0);

            fma2(A[0], (unsigned long long)u10.x, ee1);
            fma2(A[1], (unsigned long long)u10.y, ee1);
            fma2(A[2], (unsigned long long)u11.x, ee1);
            fma2(A[3], (unsigned long long)u11.y, ee1);
            fma2(A[4], (unsigned long long)u12.x, ee1);
            fma2(A[5], (unsigned long long)u12.y, ee1);
            fma2(A[6], (unsigned long long)u13.x, ee1);
            fma2(A[7], (unsigned long long)u13.y, ee1);
        }
        for (; j < cnt; j++) {
            int sj = __shfl_sync(0xffffffffu, s, j);
            float e0 = *(const float*)(exp0 + (size_t)j * 32);
            const char* r0 = hbase + ((size_t)sj << 8);
            longlong2 u0 = *(const longlong2*)(r0);
            longlong2 u1 = *(const longlong2*)(r0 + 16);
            longlong2 u2 = *(const longlong2*)(r0 + 128);
            longlong2 u3 = *(const longlong2*)(r0 + 144);
            unsigned long long ee = bcast2(e0);
            denom += e0;
            fma2(A[0], (unsigned long long)u0.x, ee);
            fma2(A[1], (unsigned long long)u0.y, ee);
            fma2(A[2], (unsigned long long)u1.x, ee);
            fma2(A[3], (unsigned long long)u1.y, ee);
            fma2(A[4], (unsigned long long)u2.x, ee);
            fma2(A[5], (unsigned long long)u2.y, ee);
            fma2(A[6], (unsigned long long)u3.x, ee);
            fma2(A[7], (unsigned long long)u3.y, ee);
        }
    }

    float inv = (re > rs) ? 1.0f / denom : 0.0f;

    // unpack, normalize, ELU, store (immediate-offset STG.128)
    char* orow = (char*)out + ((size_t)n * (NHEAD * DIM) + h * DIM) * 4 + q * 32;
    float vals[16];
#pragma unroll
    for (int k = 0; k < 8; k++) {
        float lo, hi;
        asm("mov.b64 {%0, %1}, %2;" : "=f"(lo), "=f"(hi) : "l"(A[k]));
        vals[k * 2]     = lo;
        vals[k * 2 + 1] = hi;
    }
#pragma unroll
    for (int k = 0; k < 16; k++) {
        float v = vals[k] * inv;
        vals[k] = v > 0.f ? v : expm1f(v);
    }
    *(float4*)(orow)       = make_float4(vals[0],  vals[1],  vals[2],  vals[3]);
    *(float4*)(orow + 16)  = make_float4(vals[4],  vals[5],  vals[6],  vals[7]);
    *(float4*)(orow + 128) = make_float4(vals[8],  vals[9],  vals[10], vals[11]);
    *(float4*)(orow + 144) = make_float4(vals[12], vals[13], vals[14], vals[15]);
}

// ---------------------------------------------------------------------------
extern "C" void kernel_launch(void* const* d_in, const int* in_sizes, int n_in,
                              void* d_out, int out_size) {
    const float* h_t = (const float*)d_in[0];
    const int*   ei  = (const int*)d_in[1];
    const float* att = (const float*)d_in[2];
    float*       out = (float*)d_out;

    scores_hist_kernel<<<(NEDGE + 255) / 256, 256>>>(h_t, att, ei);  // 1
    scan_kernel<<<SCAN_NBLK, SCAN_BLK>>>();                          // 2
    fill_kernel<<<(NEDGE + 255) / 256, 256>>>(ei);                   // 3
    int blocks = (N_NODES * 32 + 127) / 128;
    node_agg_kernel<<<blocks, 128>>>(h_t, out);                      // 4 (ncu)
}